// round 2
// baseline (speedup 1.0000x reference)
#include <cuda_runtime.h>
#include <cuda_fp16.h>
#include <cstdint>
#include <cstddef>

#define BATCH   16384
#define IN_F    768
#define OUT_F   768
#define NA      9                  // 8 RBF centers + silu residual feature
#define KTOT    (NA * IN_F)        // 6912
#define BK      64                 // k-chunk per stage (64 fp16 = 128B row)
#define NKSTEPS (KTOT / BK)        // 108
#define BM      128
#define BN      256
#define GEMM_THREADS 512
#define SMEM_BYTES   (98304 + 1024)

// Scratch (allocation-free rules): PHI [BATCH][KTOT] fp16 (226 MB), W [OUT_F][KTOT] fp16.
__device__ __align__(1024) __half g_phi[(size_t)BATCH * KTOT];
__device__ __align__(1024) __half g_w[(size_t)OUT_F * KTOT];

// ---------------- helpers ----------------
__device__ __forceinline__ uint32_t smem_u32(const void* p) {
    uint32_t a;
    asm("{ .reg .u64 t; cvta.to.shared.u64 t, %1; cvt.u32.u64 %0, t; }"
        : "=r"(a) : "l"(p));
    return a;
}
__device__ __forceinline__ void cp_async16(uint32_t dst, const void* src) {
    asm volatile("cp.async.cg.shared.global [%0], [%1], 16;" :: "r"(dst), "l"(src) : "memory");
}
__device__ __forceinline__ void cp_commit() {
    asm volatile("cp.async.commit_group;" ::: "memory");
}
template <int N>
__device__ __forceinline__ void cp_wait() {
    asm volatile("cp.async.wait_group %0;" :: "n"(N) : "memory");
}
__device__ __forceinline__ void ldsm_x4(uint32_t (&r)[4], uint32_t addr) {
    asm volatile("ldmatrix.sync.aligned.m8n8.x4.shared.b16 {%0,%1,%2,%3}, [%4];"
                 : "=r"(r[0]), "=r"(r[1]), "=r"(r[2]), "=r"(r[3]) : "r"(addr));
}
__device__ __forceinline__ void mma16816(float (&c)[4], const uint32_t (&a)[4],
                                         uint32_t b0, uint32_t b1) {
    asm volatile(
        "mma.sync.aligned.m16n8k16.row.col.f32.f16.f16.f32 "
        "{%0,%1,%2,%3}, {%4,%5,%6,%7}, {%8,%9}, {%0,%1,%2,%3};"
        : "+f"(c[0]), "+f"(c[1]), "+f"(c[2]), "+f"(c[3])
        : "r"(a[0]), "r"(a[1]), "r"(a[2]), "r"(a[3]), "r"(b0), "r"(b1));
}
__device__ __forceinline__ uint32_t swz(uint32_t off) {   // SW128 xor swizzle
    return off ^ ((off >> 3) & 0x70);
}

// ---------------- featurize: x -> PHI (fp16) ----------------
// k = a*IN_F + i ; a in [0,8): Gaussian RBF, a==8: silu(x)/64
__global__ void kan_featurize(const float* __restrict__ x) {
    int idx = blockIdx.x * blockDim.x + threadIdx.x;
    if (idx >= BATCH * IN_F) return;
    int b = idx / IN_F;
    int i = idx - b * IN_F;
    float xv = x[idx];
    float zg = (xv + 2.0f) * 1.75f;                     // (x - g_a)/h = (x+2)*7/4 - a
    __half* dst = g_phi + (size_t)b * KTOT + i;
#pragma unroll
    for (int a = 0; a < 8; a++) {
        float t = zg - (float)a;
        dst[(size_t)a * IN_F] = __float2half(__expf(-t * t));
    }
    float s = xv / (1.0f + __expf(-xv));                // silu
    dst[(size_t)8 * IN_F] = __float2half(s * 0.015625f); // /64 fp16 rebalance
}

// ---------------- pack weights: W[o][k] fp16 ----------------
__global__ void kan_pack_w(const float* __restrict__ wb, const float* __restrict__ ws,
                           const float* __restrict__ c) {
    int idx = blockIdx.x * blockDim.x + threadIdx.x;
    if (idx >= OUT_F * KTOT) return;
    int o = idx / KTOT;
    int k = idx - o * KTOT;
    int a = k / IN_F;
    int i = k - a * IN_F;
    float v;
    if (a < 8) v = c[((size_t)a * OUT_F + o) * IN_F + i] * ws[(size_t)o * IN_F + i];
    else       v = wb[(size_t)o * IN_F + i] * 64.0f;    // *64 fp16 rebalance
    g_w[idx] = __float2half(v);
}

// ---------------- GEMM: out[16384,768] = PHI x W^T (mma.sync fallback) ----------------
// BM=128 x BN=256, BK=64, 16 warps (4m x 4n), warp tile 32x64, fp32 accum.
__global__ void __launch_bounds__(GEMM_THREADS, 1)
kan_gemm(float* __restrict__ out) {
    extern __shared__ char smem_raw[];
    const uint32_t sbase = (smem_u32(smem_raw) + 1023u) & ~1023u;
    const uint32_t sA[2] = { sbase,         sbase + 16384 };  // 128x64 fp16, 16KB each
    const uint32_t sB[2] = { sbase + 32768, sbase + 65536 };  // 256x64 fp16, 32KB each

    const int tid = threadIdx.x;
    const int wid = tid >> 5;
    const int lid = tid & 31;
    const int wm  = wid & 3;          // 4 m-warps
    const int wn  = wid >> 2;         // 4 n-warps
    const int m0  = blockIdx.y * BM;
    const int n0  = blockIdx.x * BN;

    const __half* aCol = g_phi + (size_t)m0 * KTOT;
    const __half* bCol = g_w   + (size_t)n0 * KTOT;

    auto load_stage = [&](int kstep, int s) {
        const __half* aSrc = aCol + kstep * BK;
        const __half* bSrc = bCol + kstep * BK;
#pragma unroll
        for (int j = 0; j < 2; j++) {                 // A: 1024 x 16B chunks
            int q = tid + j * GEMM_THREADS;
            cp_async16(sA[s] + swz((uint32_t)q << 4),
                       aSrc + (size_t)(q >> 3) * KTOT + ((q & 7) << 3));
        }
#pragma unroll
        for (int j = 0; j < 4; j++) {                 // B: 2048 x 16B chunks
            int q = tid + j * GEMM_THREADS;
            cp_async16(sB[s] + swz((uint32_t)q << 4),
                       bSrc + (size_t)(q >> 3) * KTOT + ((q & 7) << 3));
        }
        cp_commit();
    };

    load_stage(0, 0);
    load_stage(1, 1);

    float acc[2][8][4];
#pragma unroll
    for (int mi = 0; mi < 2; mi++)
#pragma unroll
        for (int ni = 0; ni < 8; ni++)
#pragma unroll
            for (int r = 0; r < 4; r++) acc[mi][ni][r] = 0.0f;

    // ldmatrix lane addressing (within-tile byte offsets, swizzled per 128B row)
    const uint32_t aRowOff = (uint32_t)(wm * 32 + (lid & 15)) * 128;     // + mi*16*128
    const uint32_t aColB   = (uint32_t)((lid >> 4) * 8) * 2;             // + kk*2
    const uint32_t bRowOff = (uint32_t)(wn * 64 + (lid >> 4) * 8 + (lid & 7)) * 128;  // + nb*16*128
    const uint32_t bColB   = (uint32_t)(((lid >> 3) & 1) * 8) * 2;       // + kk*2

#pragma unroll 1
    for (int k = 0; k < NKSTEPS; k++) {
        const int s = k & 1;
        if (k < NKSTEPS - 1) cp_wait<1>(); else cp_wait<0>();
        __syncthreads();

        const uint32_t sAs = sA[s], sBs = sB[s];
#pragma unroll
        for (int kk = 0; kk < BK; kk += 16) {
            uint32_t a[2][4];
#pragma unroll
            for (int mi = 0; mi < 2; mi++)
                ldsm_x4(a[mi], sAs + swz(aRowOff + (uint32_t)(mi * 16) * 128 +
                                         aColB + (uint32_t)kk * 2));
#pragma unroll
            for (int nb = 0; nb < 4; nb++) {
                uint32_t b[4];
                ldsm_x4(b, sBs + swz(bRowOff + (uint32_t)(nb * 16) * 128 +
                                     bColB + (uint32_t)kk * 2));
                mma16816(acc[0][2 * nb],     a[0], b[0], b[1]);
                mma16816(acc[0][2 * nb + 1], a[0], b[2], b[3]);
                mma16816(acc[1][2 * nb],     a[1], b[0], b[1]);
                mma16816(acc[1][2 * nb + 1], a[1], b[2], b[3]);
            }
        }
        __syncthreads();                  // all warps done reading stage s
        if (k + 2 < NKSTEPS) load_stage(k + 2, s);
    }

    // Epilogue: C frag -> global float2 stores
    const int gr = lid >> 2;
    const int tg = lid & 3;
    float* obase = out + (size_t)(m0 + wm * 32) * OUT_F + n0 + wn * 64;
#pragma unroll
    for (int mi = 0; mi < 2; mi++) {
#pragma unroll
        for (int ni = 0; ni < 8; ni++) {
            int row0 = mi * 16 + gr;
            int col  = ni * 8 + 2 * tg;
            float2 v0 = { acc[mi][ni][0], acc[mi][ni][1] };
            float2 v1 = { acc[mi][ni][2], acc[mi][ni][3] };
            *reinterpret_cast<float2*>(obase + (size_t)row0 * OUT_F + col)       = v0;
            *reinterpret_cast<float2*>(obase + (size_t)(row0 + 8) * OUT_F + col) = v1;
        }
    }
}

extern "C" void kernel_launch(void* const* d_in, const int* in_sizes, int n_in,
                              void* d_out, int out_size) {
    const float* x  = (const float*)d_in[0];
    const float* wb = (const float*)d_in[1];
    const float* ws = (const float*)d_in[2];
    const float* c  = (const float*)d_in[3];
    float* out = (float*)d_out;

    cudaFuncSetAttribute(kan_gemm, cudaFuncAttributeMaxDynamicSharedMemorySize, SMEM_BYTES);

    kan_pack_w   <<<(OUT_F * KTOT + 255) / 256, 256>>>(wb, ws, c);
    kan_featurize<<<(BATCH * IN_F + 255) / 256, 256>>>(x);
    kan_gemm     <<<dim3(OUT_F / BN, BATCH / BM), GEMM_THREADS, SMEM_BYTES>>>(out);
}

// round 3
// speedup vs baseline: 1.1484x; 1.1484x over previous
#include <cuda_runtime.h>
#include <cuda_fp16.h>
#include <cstdint>
#include <cstddef>

#define BATCH   16384
#define IN_F    768
#define OUT_F   768
#define KTOT    (9 * IN_F)         // 6912
#define BK      64
#define NKSTEPS (KTOT / BK)        // 108
#define BM      128
#define BN      128
#define NSTAGE  3
#define GEMM_THREADS 256
#define STAGE_BYTES  32768         // A 16KB + B 16KB
#define SMEM_BYTES   (NSTAGE * STAGE_BYTES + 1024)

// Scratch (allocation-free rules): PHI [BATCH][KTOT] fp16 (226 MB), W [OUT_F][KTOT] fp16.
__device__ __align__(1024) __half g_phi[(size_t)BATCH * KTOT];
__device__ __align__(1024) __half g_w[(size_t)OUT_F * KTOT];

// ---------------- helpers ----------------
__device__ __forceinline__ uint32_t smem_u32(const void* p) {
    uint32_t a;
    asm("{ .reg .u64 t; cvta.to.shared.u64 t, %1; cvt.u32.u64 %0, t; }"
        : "=r"(a) : "l"(p));
    return a;
}
__device__ __forceinline__ void cp_async16(uint32_t dst, const void* src) {
    asm volatile("cp.async.cg.shared.global [%0], [%1], 16;" :: "r"(dst), "l"(src) : "memory");
}
__device__ __forceinline__ void cp_commit() {
    asm volatile("cp.async.commit_group;" ::: "memory");
}
template <int N>
__device__ __forceinline__ void cp_wait() {
    asm volatile("cp.async.wait_group %0;" :: "n"(N) : "memory");
}
__device__ __forceinline__ void ldsm_x4(uint32_t (&r)[4], uint32_t addr) {
    asm volatile("ldmatrix.sync.aligned.m8n8.x4.shared.b16 {%0,%1,%2,%3}, [%4];"
                 : "=r"(r[0]), "=r"(r[1]), "=r"(r[2]), "=r"(r[3]) : "r"(addr));
}
__device__ __forceinline__ void mma16816(float (&c)[4], const uint32_t (&a)[4],
                                         uint32_t b0, uint32_t b1) {
    asm volatile(
        "mma.sync.aligned.m16n8k16.row.col.f32.f16.f16.f32 "
        "{%0,%1,%2,%3}, {%4,%5,%6,%7}, {%8,%9}, {%0,%1,%2,%3};"
        : "+f"(c[0]), "+f"(c[1]), "+f"(c[2]), "+f"(c[3])
        : "r"(a[0]), "r"(a[1]), "r"(a[2]), "r"(a[3]), "r"(b0), "r"(b1));
}
__device__ __forceinline__ uint32_t swz(uint32_t off) {   // 128B-row xor swizzle
    return off ^ ((off >> 3) & 0x70);
}

// ---------------- featurize: x -> PHI (fp16) ----------------
// k = a*IN_F + i ; a in [0,8): Gaussian RBF, a==8: silu(x)/64
__global__ void kan_featurize(const float* __restrict__ x) {
    int idx = blockIdx.x * blockDim.x + threadIdx.x;
    if (idx >= BATCH * IN_F) return;
    int b = idx / IN_F;
    int i = idx - b * IN_F;
    float xv = x[idx];
    float zg = (xv + 2.0f) * 1.75f;                      // (x - g_a)/h
    __half* dst = g_phi + (size_t)b * KTOT + i;
#pragma unroll
    for (int a = 0; a < 8; a++) {
        float t = zg - (float)a;
        dst[(size_t)a * IN_F] = __float2half(__expf(-t * t));
    }
    float s = xv / (1.0f + __expf(-xv));                 // silu
    dst[(size_t)8 * IN_F] = __float2half(s * 0.015625f); // /64 fp16 rebalance
}

// ---------------- pack weights: W[o][k] fp16 ----------------
__global__ void kan_pack_w(const float* __restrict__ wb, const float* __restrict__ ws,
                           const float* __restrict__ c) {
    int idx = blockIdx.x * blockDim.x + threadIdx.x;
    if (idx >= OUT_F * KTOT) return;
    int o = idx / KTOT;
    int k = idx - o * KTOT;
    int a = k / IN_F;
    int i = k - a * IN_F;
    float v;
    if (a < 8) v = c[((size_t)a * OUT_F + o) * IN_F + i] * ws[(size_t)o * IN_F + i];
    else       v = wb[(size_t)o * IN_F + i] * 64.0f;     // *64 fp16 rebalance
    g_w[idx] = __float2half(v);
}

// ---------------- GEMM: out = PHI x W^T ----------------
// BM=128 x BN=128, BK=64, 8 warps (2m x 4n), warp tile 64x32.
// 3-stage cp.async ring, ONE __syncthreads per k-iter, 2 CTAs/SM.
__global__ void __launch_bounds__(GEMM_THREADS, 2)
kan_gemm(float* __restrict__ out) {
    extern __shared__ char smem_raw[];
    const uint32_t sbase = (smem_u32(smem_raw) + 1023u) & ~1023u;
    // stage s: A at sbase + s*32768, B at +16384

    const int tid = threadIdx.x;
    const int wid = tid >> 5;
    const int lid = tid & 31;
    const int wm  = wid & 1;          // 2 m-warps (64 rows each)
    const int wn  = wid >> 1;         // 4 n-warps (32 cols each)
    const int m0  = blockIdx.y * BM;
    const int n0  = blockIdx.x * BN;

    const __half* aCol = g_phi + (size_t)m0 * KTOT;
    const __half* bCol = g_w   + (size_t)n0 * KTOT;

    auto load_stage = [&](int kstep, int s) {
        const uint32_t sA = sbase + (uint32_t)s * STAGE_BYTES;
        const uint32_t sB = sA + 16384;
        const __half* aSrc = aCol + kstep * BK;
        const __half* bSrc = bCol + kstep * BK;
#pragma unroll
        for (int j = 0; j < 4; j++) {                 // A: 1024 x 16B chunks
            int q = tid + j * GEMM_THREADS;
            cp_async16(sA + swz((uint32_t)q << 4),
                       aSrc + (size_t)(q >> 3) * KTOT + ((q & 7) << 3));
        }
#pragma unroll
        for (int j = 0; j < 4; j++) {                 // B: 1024 x 16B chunks
            int q = tid + j * GEMM_THREADS;
            cp_async16(sB + swz((uint32_t)q << 4),
                       bSrc + (size_t)(q >> 3) * KTOT + ((q & 7) << 3));
        }
    };

    load_stage(0, 0); cp_commit();
    load_stage(1, 1); cp_commit();

    float acc[4][4][4];
#pragma unroll
    for (int mi = 0; mi < 4; mi++)
#pragma unroll
        for (int ni = 0; ni < 4; ni++)
#pragma unroll
            for (int r = 0; r < 4; r++) acc[mi][ni][r] = 0.0f;

    // ldmatrix lane addressing (byte offsets within tile, swizzled per 128B row)
    const uint32_t aRowOff = (uint32_t)(wm * 64 + (lid & 15)) * 128;            // + mi*16*128
    const uint32_t aColB   = (uint32_t)(lid >> 4) * 16;                          // + kk*2
    const uint32_t bRowOff = (uint32_t)(wn * 32 + (lid >> 4) * 8 + (lid & 7)) * 128; // + nb*16*128
    const uint32_t bColB   = (uint32_t)((lid >> 3) & 1) * 16;                    // + kk*2

    int stage = 0;
#pragma unroll 1
    for (int k = 0; k < NKSTEPS; k++) {
        cp_wait<1>();
        __syncthreads();

        // prefetch stage k+2 into the buffer freed by iter k-1 (safe: barrier above)
        if (k + 2 < NKSTEPS) {
            int s2 = stage + 2; if (s2 >= NSTAGE) s2 -= NSTAGE;
            load_stage(k + 2, s2);
        }
        cp_commit();   // unconditional: keeps wait_group counting uniform at the tail

        const uint32_t sA = sbase + (uint32_t)stage * STAGE_BYTES;
        const uint32_t sB = sA + 16384;
#pragma unroll
        for (int kk = 0; kk < BK; kk += 16) {
            uint32_t a[4][4];
#pragma unroll
            for (int mi = 0; mi < 4; mi++)
                ldsm_x4(a[mi], sA + swz(aRowOff + (uint32_t)(mi * 16) * 128 +
                                        aColB + (uint32_t)kk * 2));
#pragma unroll
            for (int nb = 0; nb < 2; nb++) {
                uint32_t b[4];
                ldsm_x4(b, sB + swz(bRowOff + (uint32_t)(nb * 16) * 128 +
                                    bColB + (uint32_t)kk * 2));
#pragma unroll
                for (int mi = 0; mi < 4; mi++) {
                    mma16816(acc[mi][2 * nb],     a[mi], b[0], b[1]);
                    mma16816(acc[mi][2 * nb + 1], a[mi], b[2], b[3]);
                }
            }
        }
        if (++stage == NSTAGE) stage = 0;
    }

    // Epilogue: C frags -> global float2 stores
    const int gr = lid >> 2;
    const int tg = lid & 3;
    float* obase = out + (size_t)(m0 + wm * 64) * OUT_F + n0 + wn * 32;
#pragma unroll
    for (int mi = 0; mi < 4; mi++) {
#pragma unroll
        for (int ni = 0; ni < 4; ni++) {
            int row0 = mi * 16 + gr;
            int col  = ni * 8 + 2 * tg;
            float2 v0 = { acc[mi][ni][0], acc[mi][ni][1] };
            float2 v1 = { acc[mi][ni][2], acc[mi][ni][3] };
            *reinterpret_cast<float2*>(obase + (size_t)row0 * OUT_F + col)       = v0;
            *reinterpret_cast<float2*>(obase + (size_t)(row0 + 8) * OUT_F + col) = v1;
        }
    }
}

extern "C" void kernel_launch(void* const* d_in, const int* in_sizes, int n_in,
                              void* d_out, int out_size) {
    const float* x  = (const float*)d_in[0];
    const float* wb = (const float*)d_in[1];
    const float* ws = (const float*)d_in[2];
    const float* c  = (const float*)d_in[3];
    float* out = (float*)d_out;

    cudaFuncSetAttribute(kan_gemm, cudaFuncAttributeMaxDynamicSharedMemorySize, SMEM_BYTES);

    kan_pack_w   <<<(OUT_F * KTOT + 255) / 256, 256>>>(wb, ws, c);
    kan_featurize<<<(BATCH * IN_F + 255) / 256, 256>>>(x);
    kan_gemm     <<<dim3(OUT_F / BN, BATCH / BM), GEMM_THREADS, SMEM_BYTES>>>(out);
}

// round 4
// speedup vs baseline: 1.1668x; 1.0160x over previous
#include <cuda_runtime.h>
#include <cuda_fp16.h>
#include <cstdint>
#include <cstddef>

#define BATCH   16384
#define IN_F    768
#define OUT_F   768
#define KTOT    (9 * IN_F)         // 6912
#define BK      64
#define NKSTEPS (KTOT / BK)        // 108
#define BM      128
#define BN      128
#define NSTAGE  3
#define GEMM_THREADS 256
#define STAGE_BYTES  32768         // A 16KB + B 16KB
#define SMEM_BYTES   (NSTAGE * STAGE_BYTES + 1024)

// Scratch (allocation-free rules): PHI [BATCH][KTOT] fp16 (226 MB), W [OUT_F][KTOT] fp16.
__device__ __align__(1024) __half g_phi[(size_t)BATCH * KTOT];
__device__ __align__(1024) __half g_w[(size_t)OUT_F * KTOT];

// ---------------- helpers ----------------
__device__ __forceinline__ uint32_t smem_u32(const void* p) {
    uint32_t a;
    asm("{ .reg .u64 t; cvta.to.shared.u64 t, %1; cvt.u32.u64 %0, t; }"
        : "=r"(a) : "l"(p));
    return a;
}
__device__ __forceinline__ void cp_async16(uint32_t dst, const void* src) {
    asm volatile("cp.async.cg.shared.global [%0], [%1], 16;" :: "r"(dst), "l"(src) : "memory");
}
__device__ __forceinline__ void cp_commit() {
    asm volatile("cp.async.commit_group;" ::: "memory");
}
template <int N>
__device__ __forceinline__ void cp_wait() {
    asm volatile("cp.async.wait_group %0;" :: "n"(N) : "memory");
}
__device__ __forceinline__ void ldsm_x4(uint32_t (&r)[4], uint32_t addr) {
    asm volatile("ldmatrix.sync.aligned.m8n8.x4.shared.b16 {%0,%1,%2,%3}, [%4];"
                 : "=r"(r[0]), "=r"(r[1]), "=r"(r[2]), "=r"(r[3]) : "r"(addr));
}
__device__ __forceinline__ void mma16816(float (&c)[4], const uint32_t (&a)[4],
                                         uint32_t b0, uint32_t b1) {
    asm volatile(
        "mma.sync.aligned.m16n8k16.row.col.f32.f16.f16.f32 "
        "{%0,%1,%2,%3}, {%4,%5,%6,%7}, {%8,%9}, {%0,%1,%2,%3};"
        : "+f"(c[0]), "+f"(c[1]), "+f"(c[2]), "+f"(c[3])
        : "r"(a[0]), "r"(a[1]), "r"(a[2]), "r"(a[3]), "r"(b0), "r"(b1));
}
__device__ __forceinline__ uint32_t swz(uint32_t off) {   // 128B-row xor swizzle
    return off ^ ((off >> 3) & 0x70);
}

// ---------------- featurize: x -> PHI (fp16) ----------------
// k = a*IN_F + i ; a in [0,8): Gaussian RBF, a==8: silu(x)/64
__global__ void kan_featurize(const float* __restrict__ x) {
    int idx = blockIdx.x * blockDim.x + threadIdx.x;
    if (idx >= BATCH * IN_F) return;
    int b = idx / IN_F;
    int i = idx - b * IN_F;
    float xv = x[idx];
    float zg = (xv + 2.0f) * 1.75f;                      // (x - g_a)/h
    __half* dst = g_phi + (size_t)b * KTOT + i;
#pragma unroll
    for (int a = 0; a < 8; a++) {
        float t = zg - (float)a;
        dst[(size_t)a * IN_F] = __float2half(__expf(-t * t));
    }
    float s = xv / (1.0f + __expf(-xv));                 // silu
    dst[(size_t)8 * IN_F] = __float2half(s * 0.015625f); // /64 fp16 rebalance
}

// ---------------- pack weights: W[o][k] fp16 ----------------
__global__ void kan_pack_w(const float* __restrict__ wb, const float* __restrict__ ws,
                           const float* __restrict__ c) {
    int idx = blockIdx.x * blockDim.x + threadIdx.x;
    if (idx >= OUT_F * KTOT) return;
    int o = idx / KTOT;
    int k = idx - o * KTOT;
    int a = k / IN_F;
    int i = k - a * IN_F;
    float v;
    if (a < 8) v = c[((size_t)a * OUT_F + o) * IN_F + i] * ws[(size_t)o * IN_F + i];
    else       v = wb[(size_t)o * IN_F + i] * 64.0f;     // *64 fp16 rebalance
    g_w[idx] = __float2half(v);
}

// ---------------- GEMM: out = PHI x W^T ----------------
// BM=128 x BN=128, BK=64, 8 warps (2m x 4n), warp tile 64x32.
// 3-stage cp.async ring, 1 barrier/k-iter, 2 CTAs/SM,
// register double-buffered fragments (ldsm for kk+1 overlaps mma of kk).
__global__ void __launch_bounds__(GEMM_THREADS, 2)
kan_gemm(float* __restrict__ out) {
    extern __shared__ char smem_raw[];
    const uint32_t sbase = (smem_u32(smem_raw) + 1023u) & ~1023u;

    const int tid = threadIdx.x;
    const int wid = tid >> 5;
    const int lid = tid & 31;
    const int wm  = wid & 1;          // 2 m-warps (64 rows each)
    const int wn  = wid >> 1;         // 4 n-warps (32 cols each)
    const int m0  = blockIdx.y * BM;
    const int n0  = blockIdx.x * BN;

    const __half* aCol = g_phi + (size_t)m0 * KTOT;
    const __half* bCol = g_w   + (size_t)n0 * KTOT;

    auto load_stage = [&](int kstep, int s) {
        const uint32_t sA = sbase + (uint32_t)s * STAGE_BYTES;
        const uint32_t sB = sA + 16384;
        const __half* aSrc = aCol + kstep * BK;
        const __half* bSrc = bCol + kstep * BK;
#pragma unroll
        for (int j = 0; j < 4; j++) {
            int q = tid + j * GEMM_THREADS;
            cp_async16(sA + swz((uint32_t)q << 4),
                       aSrc + (size_t)(q >> 3) * KTOT + ((q & 7) << 3));
        }
#pragma unroll
        for (int j = 0; j < 4; j++) {
            int q = tid + j * GEMM_THREADS;
            cp_async16(sB + swz((uint32_t)q << 4),
                       bSrc + (size_t)(q >> 3) * KTOT + ((q & 7) << 3));
        }
    };

    load_stage(0, 0); cp_commit();
    load_stage(1, 1); cp_commit();

    float acc[4][4][4];
#pragma unroll
    for (int mi = 0; mi < 4; mi++)
#pragma unroll
        for (int ni = 0; ni < 4; ni++)
#pragma unroll
            for (int r = 0; r < 4; r++) acc[mi][ni][r] = 0.0f;

    // ldmatrix lane addressing (byte offsets within tile, swizzled per 128B row)
    const uint32_t aRowOff = (uint32_t)(wm * 64 + (lid & 15)) * 128;            // + mi*16*128
    const uint32_t aColB   = (uint32_t)(lid >> 4) * 16;                          // + kk*2
    const uint32_t bRowOff = (uint32_t)(wn * 32 + (lid >> 4) * 8 + (lid & 7)) * 128; // + nb*16*128
    const uint32_t bColB   = (uint32_t)((lid >> 3) & 1) * 16;                    // + kk*2

    uint32_t afrag[2][4][4];   // [buf][mi][reg]
    uint32_t bfrag[2][2][4];   // [buf][nb][reg]

    auto load_frags = [&](int buf, uint32_t sA, uint32_t sB, int kk) {
#pragma unroll
        for (int mi = 0; mi < 4; mi++)
            ldsm_x4(afrag[buf][mi], sA + swz(aRowOff + (uint32_t)(mi * 16) * 128 +
                                             aColB + (uint32_t)kk * 32));
#pragma unroll
        for (int nb = 0; nb < 2; nb++)
            ldsm_x4(bfrag[buf][nb], sB + swz(bRowOff + (uint32_t)(nb * 16) * 128 +
                                             bColB + (uint32_t)kk * 32));
    };
    auto mma_step = [&](int buf) {
#pragma unroll
        for (int nb = 0; nb < 2; nb++)
#pragma unroll
            for (int mi = 0; mi < 4; mi++) {
                mma16816(acc[mi][2 * nb],     afrag[buf][mi],
                         bfrag[buf][nb][0], bfrag[buf][nb][1]);
                mma16816(acc[mi][2 * nb + 1], afrag[buf][mi],
                         bfrag[buf][nb][2], bfrag[buf][nb][3]);
            }
    };

    int stage = 0;
#pragma unroll 1
    for (int k = 0; k < NKSTEPS; k++) {
        cp_wait<1>();
        __syncthreads();

        // prefetch stage k+2 into the buffer freed last iter (safe: barrier above)
        if (k + 2 < NKSTEPS) {
            int s2 = stage + 2; if (s2 >= NSTAGE) s2 -= NSTAGE;
            load_stage(k + 2, s2);
        }
        cp_commit();   // unconditional: uniform wait_group counting at the tail

        const uint32_t sA = sbase + (uint32_t)stage * STAGE_BYTES;
        const uint32_t sB = sA + 16384;

        load_frags(0, sA, sB, 0);
#pragma unroll
        for (int kk = 0; kk < 4; kk++) {
            if (kk < 3) load_frags((kk + 1) & 1, sA, sB, kk + 1);
            mma_step(kk & 1);
        }
        if (++stage == NSTAGE) stage = 0;
    }

    // Epilogue: C frags -> global float2 stores
    const int gr = lid >> 2;
    const int tg = lid & 3;
    float* obase = out + (size_t)(m0 + wm * 64) * OUT_F + n0 + wn * 32;
#pragma unroll
    for (int mi = 0; mi < 4; mi++) {
#pragma unroll
        for (int ni = 0; ni < 4; ni++) {
            int row0 = mi * 16 + gr;
            int col  = ni * 8 + 2 * tg;
            float2 v0 = { acc[mi][ni][0], acc[mi][ni][1] };
            float2 v1 = { acc[mi][ni][2], acc[mi][ni][3] };
            *reinterpret_cast<float2*>(obase + (size_t)row0 * OUT_F + col)       = v0;
            *reinterpret_cast<float2*>(obase + (size_t)(row0 + 8) * OUT_F + col) = v1;
        }
    }
}

extern "C" void kernel_launch(void* const* d_in, const int* in_sizes, int n_in,
                              void* d_out, int out_size) {
    const float* x  = (const float*)d_in[0];
    const float* wb = (const float*)d_in[1];
    const float* ws = (const float*)d_in[2];
    const float* c  = (const float*)d_in[3];
    float* out = (float*)d_out;

    cudaFuncSetAttribute(kan_gemm, cudaFuncAttributeMaxDynamicSharedMemorySize, SMEM_BYTES);

    kan_pack_w   <<<(OUT_F * KTOT + 255) / 256, 256>>>(wb, ws, c);
    kan_featurize<<<(BATCH * IN_F + 255) / 256, 256>>>(x);
    kan_gemm     <<<dim3(OUT_F / BN, BATCH / BM), GEMM_THREADS, SMEM_BYTES>>>(out);
}